// round 13
// baseline (speedup 1.0000x reference)
#include <cuda_runtime.h>
#include <cuda_fp16.h>
#include <cstdint>

#define SEQ 2048
#define DM 1024
#define NH 16
#define HD 64
#define NANCH 3
#define QPB 4

// ---------------- scratch ------------------------------------------------------
__device__ __half g_qh16[SEQ * DM];          // Q after RoPE, fp16 [S, H*D]
__device__ __half g_khh[NH * SEQ * HD];      // K after RoPE, fp16 [H,S,D] (128B rows)
__device__ __half g_vhh[NH * SEQ * HD];      // V fp16 [H,S,D] (128B rows)
__device__ __half g_xh[SEQ * DM];            // x fp16
__device__ __half g_wth[3072 * DM];          // [n,k] Wq|Wk|Wv^T fp16
__device__ __half g_woth[DM * DM];           // [n,k] Wo^T fp16
__device__ __half g_ath[SEQ * DM];           // attn out fp16 [S, H*D]

// ---------------- PTX helpers --------------------------------------------------
__device__ __forceinline__ uint32_t smem_u32(const void* p) {
    uint32_t a;
    asm("{ .reg .u64 t; cvta.to.shared.u64 t, %1; cvt.u32.u64 %0, t; }" : "=r"(a) : "l"(p));
    return a;
}
__device__ __forceinline__ void cp16(uint32_t s, const void* g) {
    asm volatile("cp.async.cg.shared.global [%0], [%1], 16;" :: "r"(s), "l"(g));
}
#define CP_COMMIT() asm volatile("cp.async.commit_group;" ::: "memory")
#define CP_WAIT2()  asm volatile("cp.async.wait_group 2;" ::: "memory")
#define CP_WAIT1()  asm volatile("cp.async.wait_group 1;" ::: "memory")
#define CP_WAIT0()  asm volatile("cp.async.wait_group 0;" ::: "memory")

__device__ __forceinline__ void ldsm_x4(uint32_t& r0, uint32_t& r1, uint32_t& r2,
                                        uint32_t& r3, uint32_t a) {
    asm volatile("ldmatrix.sync.aligned.m8n8.x4.shared.b16 {%0,%1,%2,%3}, [%4];"
                 : "=r"(r0), "=r"(r1), "=r"(r2), "=r"(r3) : "r"(a));
}
__device__ __forceinline__ void ldsm_x4_t(uint32_t& r0, uint32_t& r1, uint32_t& r2,
                                          uint32_t& r3, uint32_t a) {
    asm volatile("ldmatrix.sync.aligned.m8n8.x4.trans.shared.b16 {%0,%1,%2,%3}, [%4];"
                 : "=r"(r0), "=r"(r1), "=r"(r2), "=r"(r3) : "r"(a));
}
__device__ __forceinline__ void mma_f16(float* d, const uint32_t* a, const uint32_t* b) {
    asm volatile(
        "mma.sync.aligned.m16n8k16.row.col.f32.f16.f16.f32 "
        "{%0,%1,%2,%3}, {%4,%5,%6,%7}, {%8,%9}, {%0,%1,%2,%3};"
        : "+f"(d[0]), "+f"(d[1]), "+f"(d[2]), "+f"(d[3])
        : "r"(a[0]), "r"(a[1]), "r"(a[2]), "r"(a[3]), "r"(b[0]), "r"(b[1]));
}

// ---------------- prep -----------------------------------------------------------
__global__ void split_x(const float* __restrict__ x) {
    int i = blockIdx.x * 256 + threadIdx.x;
    const float4 v = ((const float4*)x)[i];
    __half2* o = (__half2*)(g_xh + 4 * (size_t)i);
    o[0] = __floats2half2_rn(v.x, v.y);
    o[1] = __floats2half2_rn(v.z, v.w);
}

// W [k][n] -> Wt [n][k] fp16. z 0..2 -> Wq/Wk/Wv; z==3 -> Wo
__global__ void transpose_w(const float* __restrict__ Wq, const float* __restrict__ Wk,
                            const float* __restrict__ Wv, const float* __restrict__ Wo) {
    __shared__ float tile[32][33];
    int z = blockIdx.z;
    const float* W = (z == 0) ? Wq : (z == 1) ? Wk : (z == 2) ? Wv : Wo;
    __half* dst = (z < 3) ? (g_wth + (size_t)z * DM * DM) : g_woth;
    int k0 = blockIdx.y * 32, n0 = blockIdx.x * 32;
    int tx = threadIdx.x, ty = threadIdx.y;
    tile[ty][tx] = W[(size_t)(k0 + ty) * DM + n0 + tx];
    __syncthreads();
    dst[(size_t)(n0 + ty) * DM + k0 + tx] = __float2half(tile[tx][ty]);
}

// ---------------- fp16 GEMM: C[M,N] = A[M,K] @ B[N,K]^T --------------------------
#define F_BK 64
#define F_STG 32768
#define F_OFF_B 16384
#define F_NSTAGE 4

__device__ __forceinline__ uint32_t swz8(uint32_t row, uint32_t seg) {
    return row * 128 + ((seg ^ (row & 7)) << 4);
}

__device__ __forceinline__ void f16_load_chunk(
    uint32_t stage, int tid, int c, int m0, int n0, int K,
    const __half* A, const __half* B)
{
    #pragma unroll
    for (int mtx = 0; mtx < 2; mtx++) {
        const int r0 = (mtx == 0) ? m0 : n0;
        const __half* src = (mtx == 0) ? A : B;
        const uint32_t off = mtx ? F_OFF_B : 0;
        #pragma unroll
        for (int i = 0; i < 4; i++) {
            int lin = i * 256 + tid;
            int row = lin >> 3, seg = lin & 7;
            const void* g = src + (size_t)(r0 + row) * K + c * F_BK + seg * 8;
            cp16(stage + off + swz8(row, seg), g);
        }
    }
}

__global__ void __launch_bounds__(256) gemm_f16(
    const __half* __restrict__ A, const __half* __restrict__ B,
    float* __restrict__ C, int Nstride, int K, int mode,
    __half* __restrict__ Qout, __half* __restrict__ Kout, __half* __restrict__ Vout,
    const float* __restrict__ cosT, const float* __restrict__ sinT)
{
    extern __shared__ __align__(1024) char dsm[];
    const uint32_t tiles = smem_u32(dsm);

    const int tid = threadIdx.x;
    const int m0 = blockIdx.y * 128, n0 = blockIdx.x * 128;
    const int nCh = K / F_BK;

    const int w = tid >> 5, lane = tid & 31;
    const int wm = (w & 3) * 32;
    const int wn = (w >> 2) * 64;

    float acc[2][8][4];
    #pragma unroll
    for (int i = 0; i < 2; i++)
        #pragma unroll
        for (int j = 0; j < 8; j++)
            #pragma unroll
            for (int e = 0; e < 4; e++) acc[i][j][e] = 0.f;

    f16_load_chunk(tiles, tid, 0, m0, n0, K, A, B); CP_COMMIT();
    f16_load_chunk(tiles + F_STG, tid, 1, m0, n0, K, A, B); CP_COMMIT();
    f16_load_chunk(tiles + 2 * F_STG, tid, 2, m0, n0, K, A, B); CP_COMMIT();

    const int aRowL = lane & 15;
    const int aSegL = lane >> 4;
    const int bRowL = ((lane >> 4) & 1) * 8 + (lane & 7);
    const int bSegL = (lane >> 3) & 1;

    for (int c = 0; c < nCh; c++) {
        const uint32_t buf = tiles + (c % F_NSTAGE) * F_STG;
        CP_WAIT2();
        __syncthreads();
        if (c + 3 < nCh)
            f16_load_chunk(tiles + ((c + 3) % F_NSTAGE) * F_STG, tid, c + 3, m0, n0, K, A, B);
        CP_COMMIT();

        #pragma unroll
        for (int k16 = 0; k16 < 4; k16++) {
            uint32_t af[2][4], bf[4][4];
            #pragma unroll
            for (int mt = 0; mt < 2; mt++) {
                uint32_t row = wm + mt * 16 + aRowL;
                ldsm_x4(af[mt][0], af[mt][1], af[mt][2], af[mt][3],
                        buf + swz8(row, k16 * 2 + aSegL));
            }
            #pragma unroll
            for (int np = 0; np < 4; np++) {
                uint32_t row = wn + np * 16 + bRowL;
                ldsm_x4(bf[np][0], bf[np][1], bf[np][2], bf[np][3],
                        buf + F_OFF_B + swz8(row, k16 * 2 + bSegL));
            }
            #pragma unroll
            for (int mt = 0; mt < 2; mt++)
                #pragma unroll
                for (int np = 0; np < 4; np++)
                    #pragma unroll
                    for (int h = 0; h < 2; h++)
                        mma_f16(acc[mt][np * 2 + h], af[mt], &bf[np][h * 2]);
        }
        __syncthreads();
    }

    const int erow = lane >> 2, ecol = (lane & 3) * 2;

    if (mode == 0) {
        const int ncol = n0 + wn;
        const int zsel = ncol >> 10;
        const int hh = (ncol >> 6) & 15;
        #pragma unroll
        for (int mt = 0; mt < 2; mt++) {
            #pragma unroll
            for (int rsel = 0; rsel < 2; rsel++) {
                const int s = m0 + wm + mt * 16 + erow + rsel * 8;
                if (zsel == 2) {
                    __half* vb = Vout + ((size_t)hh * SEQ + s) * HD;
                    #pragma unroll
                    for (int nt = 0; nt < 8; nt++)
                        *(__half2*)(vb + nt * 8 + ecol) =
                            __floats2half2_rn(acc[mt][nt][rsel * 2], acc[mt][nt][rsel * 2 + 1]);
                } else {
                    __half* ob = (zsel == 0) ? (Qout + (size_t)s * DM + hh * HD)
                                             : (Kout + ((size_t)hh * SEQ + s) * HD);
                    #pragma unroll
                    for (int nt = 0; nt < 4; nt++) {
                        const int d0 = nt * 8 + ecol;
                        const float c0 = cosT[s * 32 + d0],     sn0 = sinT[s * 32 + d0];
                        const float c1 = cosT[s * 32 + d0 + 1], sn1 = sinT[s * 32 + d0 + 1];
                        const float a0 = acc[mt][nt][rsel * 2],     a1 = acc[mt][nt][rsel * 2 + 1];
                        const float b0 = acc[mt][nt + 4][rsel * 2], b1 = acc[mt][nt + 4][rsel * 2 + 1];
                        *(__half2*)(ob + d0) =
                            __floats2half2_rn(a0 * c0 - b0 * sn0, a1 * c1 - b1 * sn1);
                        *(__half2*)(ob + d0 + 32) =
                            __floats2half2_rn(b0 * c0 + a0 * sn0, b1 * c1 + a1 * sn1);
                    }
                }
            }
        }
    } else {
        #pragma unroll
        for (int mt = 0; mt < 2; mt++)
            #pragma unroll
            for (int nt = 0; nt < 8; nt++) {
                const float* d = acc[mt][nt];
                size_t r = (size_t)(m0 + wm + mt * 16 + erow);
                size_t col = n0 + wn + nt * 8 + ecol;
                *(float2*)&C[r * Nstride + col]       = make_float2(d[0], d[1]);
                *(float2*)&C[(r + 8) * Nstride + col] = make_float2(d[2], d[3]);
            }
    }
}

// ---------------- sparse attention -----------------------------------------------
// Both QK^T and P*V on mma.sync. Dynamic smem layout (per block):
//   [ql*16384 +    0 .. 8192)  K tiles (4 x 16 x 128B, swizzled)
//   [ql*16384 + 8192 ..16384)  V tiles (same layout)
//   65536: sqh   (QPB x 32 half2)
//   66048: sw16  (QPB x 64 half)
//   66560: stile (QPB x 4 int)
//   66624: wred  (QPB x 2 x 2 float)
//   66688: spart (QPB x 2 x 64 float)
#define ATTN_SMEM 68736

__global__ void __launch_bounds__(256) attn(const int* __restrict__ anchors) {
    extern __shared__ __align__(128) char dyn[];
    const int h = blockIdx.y;
    const int tid = threadIdx.x;
    const int ql = tid >> 6;
    const int j = tid & 63;
    const int s = blockIdx.x * QPB + ql;
    const int wq = (tid >> 5) & 1;
    const int lane = tid & 31;
    const int tig = lane & 3;

    __half2* sqh  = (__half2*)(dyn + 65536) + ql * 32;
    __half*  sw16 = (__half*)(dyn + 66048) + ql * 64;
    int*     stile = (int*)(dyn + 66560) + ql * 4;
    float*   wred = (float*)(dyn + 66624) + ql * 4;   // [row*2 + wq]
    float*   spart = (float*)(dyn + 66688) + ql * 128; // [wq*64 + dim]

    // q (half2) and tile indices
    if (j < 32)
        sqh[j] = ((const __half2*)(g_qh16 + (size_t)s * DM + h * HD))[j];
    if (j < 4)
        stile[j] = (j < NANCH) ? anchors[(h * SEQ + s) * NANCH + j] : (s >> 4);
    __syncthreads();

    const int t0 = stile[0], t1 = stile[1], t2 = stile[2], t3 = stile[3];

    // stage K tiles (group A) then V tiles (group B); both 4 x 2KB contiguous
    const uint32_t sbase = smem_u32(dyn) + ql * 16384;
    {
        const uint32_t so = (j >> 3) * 128 + (((j & 7) ^ (j >> 3)) << 4);
        const uint32_t go = j * 16;
        const char* kb0 = (const char*)g_khh + (size_t)h * SEQ * 128 + go;
        cp16(sbase + so,        kb0 + t0 * 2048);
        cp16(sbase + 1024 + so, kb0 + t0 * 2048 + 1024);
        cp16(sbase + 2048 + so, kb0 + t1 * 2048);
        cp16(sbase + 3072 + so, kb0 + t1 * 2048 + 1024);
        cp16(sbase + 4096 + so, kb0 + t2 * 2048);
        cp16(sbase + 5120 + so, kb0 + t2 * 2048 + 1024);
        cp16(sbase + 6144 + so, kb0 + t3 * 2048);
        cp16(sbase + 7168 + so, kb0 + t3 * 2048 + 1024);
        CP_COMMIT();
        const char* vb0 = (const char*)g_vhh + (size_t)h * SEQ * 128 + go;
        const uint32_t sv = sbase + 8192;
        cp16(sv + so,        vb0 + t0 * 2048);
        cp16(sv + 1024 + so, vb0 + t0 * 2048 + 1024);
        cp16(sv + 2048 + so, vb0 + t1 * 2048);
        cp16(sv + 3072 + so, vb0 + t1 * 2048 + 1024);
        cp16(sv + 4096 + so, vb0 + t2 * 2048);
        cp16(sv + 5120 + so, vb0 + t2 * 2048 + 1024);
        cp16(sv + 6144 + so, vb0 + t3 * 2048);
        cp16(sv + 7168 + so, vb0 + t3 * 2048 + 1024);
        CP_COMMIT();
    }
    CP_WAIT1();          // K tiles ready (V still in flight)
    __syncthreads();

    // B fragments: q replicated across all 8 n-columns
    uint32_t bq[4][2];
    #pragma unroll
    for (int c = 0; c < 4; c++) {
        bq[c][0] = *(const uint32_t*)&sqh[c * 8 + tig];
        bq[c][1] = *(const uint32_t*)&sqh[c * 8 + tig + 4];
    }

    // logits via mma: 2 m-tiles of 16 keys, 4 k-chunks each
    float lg[4];                             // keys: wq*32 + {r, r+8, 16+r, 24+r}
    #pragma unroll
    for (int t = 0; t < 2; t++) {
        float c4[4] = {0.f, 0.f, 0.f, 0.f};
        #pragma unroll
        for (int c = 0; c < 4; c++) {
            uint32_t a[4];
            ldsm_x4(a[0], a[1], a[2], a[3],
                    sbase + swz8(wq * 32 + t * 16 + (lane & 15), c * 2 + (lane >> 4)));
            mma_f16(c4, a, bq[c]);
        }
        lg[t * 2]     = c4[0] * 0.125f;
        lg[t * 2 + 1] = c4[2] * 0.125f;
    }

    CP_WAIT0();          // V tiles ready (visibility sealed by syncthreads below)

    const int r = lane >> 2;
    const int ti0 = wq ? t2 : t0, ti1 = wq ? t3 : t1;
    int kid[4] = {ti0 * 16 + r, ti0 * 16 + r + 8, ti1 * 16 + r, ti1 * 16 + r + 8};
    bool msk[4];
    #pragma unroll
    for (int i = 0; i < 4; i++) {
        msk[i] = kid[i] > s;
        if (msk[i]) lg[i] = -1e30f;
    }

    // softmax (each key duplicated x4 across the quad -> sum scaled by 0.25)
    float m = fmaxf(fmaxf(lg[0], lg[1]), fmaxf(lg[2], lg[3]));
    #pragma unroll
    for (int off = 16; off; off >>= 1) m = fmaxf(m, __shfl_xor_sync(~0u, m, off));
    if (lane == 0) wred[wq] = m;
    __syncthreads();
    m = fmaxf(wred[0], wred[1]);

    float e[4];
    float lsum = 0.f;
    #pragma unroll
    for (int i = 0; i < 4; i++) {
        e[i] = msk[i] ? 0.f : __expf(lg[i] - m);
        lsum += e[i];
    }
    #pragma unroll
    for (int off = 16; off; off >>= 1) lsum += __shfl_xor_sync(~0u, lsum, off);
    if (lane == 0) wred[2 + wq] = lsum;
    __syncthreads();
    const float inv = 4.0f / (wred[2] + wred[3]);   // 1/(sum*0.25)

    // quad leaders publish fp16 weights for their 4 key slots
    if (tig == 0) {
        sw16[wq * 32 + r]      = __float2half(e[0] * inv);
        sw16[wq * 32 + r + 8]  = __float2half(e[1] * inv);
        sw16[wq * 32 + r + 16] = __float2half(e[2] * inv);
        sw16[wq * 32 + r + 24] = __float2half(e[3] * inv);
    }
    __syncwarp();

    // P*V via mma: A = V^T (ldmatrix.trans), B = weights replicated over n.
    // Warp wq: its 32 keys (2 k-chunks) x all 64 dims (4 m-tiles).
    {
        const uint32_t sVb = sbase + 8192;
        const int kb = wq * 32;
        uint32_t bw[2][2];
        #pragma unroll
        for (int c = 0; c < 2; c++) {
            bw[c][0] = *(const uint32_t*)&sw16[kb + c * 16 + 2 * tig];
            bw[c][1] = *(const uint32_t*)&sw16[kb + c * 16 + 8 + 2 * tig];
        }
        const int g = lane >> 3;
        const int keyoff = (lane & 7) + ((g & 2) << 2);
        const int segadd = g & 1;
        #pragma unroll
        for (int mt = 0; mt < 4; mt++) {
            float c4[4] = {0.f, 0.f, 0.f, 0.f};
            #pragma unroll
            for (int c = 0; c < 2; c++) {
                const int row = kb + c * 16 + keyoff;
                const uint32_t seg = 2 * mt + segadd;
                uint32_t a[4];
                ldsm_x4_t(a[0], a[1], a[2], a[3],
                          sVb + row * 128 + ((seg ^ (row & 7)) << 4));
                mma_f16(c4, a, bw[c]);
            }
            if (tig == 0) {
                spart[wq * 64 + mt * 16 + r]     = c4[0];
                spart[wq * 64 + mt * 16 + 8 + r] = c4[2];
            }
        }
    }
    __syncthreads();

    g_ath[(size_t)s * DM + h * HD + j] =
        __float2half(spart[j] + spart[64 + j]);
}

// ---------------- launch ---------------------------------------------------------
extern "C" void kernel_launch(void* const* d_in, const int* in_sizes, int n_in,
                              void* d_out, int out_size)
{
    const float* x    = (const float*)d_in[0];
    const float* Wq   = (const float*)d_in[1];
    const float* Wk   = (const float*)d_in[2];
    const float* Wv   = (const float*)d_in[3];
    const float* Wo   = (const float*)d_in[4];
    const float* cosT = (const float*)d_in[5];
    const float* sinT = (const float*)d_in[6];
    const int* anchors = (const int*)d_in[7];
    float* out = (float*)d_out;

    const int SMEM_F = F_NSTAGE * F_STG;   // 128 KB
    cudaFuncSetAttribute(gemm_f16, cudaFuncAttributeMaxDynamicSharedMemorySize, SMEM_F);
    cudaFuncSetAttribute(attn, cudaFuncAttributeMaxDynamicSharedMemorySize, ATTN_SMEM);

    __half *xh = nullptr, *wth = nullptr, *woth = nullptr, *ath = nullptr;
    __half *qh = nullptr, *kh = nullptr, *vh = nullptr;
    cudaGetSymbolAddress((void**)&xh, g_xh);
    cudaGetSymbolAddress((void**)&wth, g_wth);
    cudaGetSymbolAddress((void**)&woth, g_woth);
    cudaGetSymbolAddress((void**)&ath, g_ath);
    cudaGetSymbolAddress((void**)&qh, g_qh16);
    cudaGetSymbolAddress((void**)&kh, g_khh);
    cudaGetSymbolAddress((void**)&vh, g_vhh);

    split_x<<<(SEQ * DM / 4) / 256, 256>>>(x);
    transpose_w<<<dim3(32, 32, 4), dim3(32, 32)>>>(Wq, Wk, Wv, Wo);

    // QKV GEMM with fused RoPE/split/fp16 epilogue
    gemm_f16<<<dim3(24, 16), 256, SMEM_F>>>(xh, wth, nullptr, 3072, DM, 0,
                                            qh, kh, vh, cosT, sinT);

    attn<<<dim3(SEQ / QPB, NH), 256, ATTN_SMEM>>>(anchors);

    // out = att @ Wo (plain fp32 epilogue)
    gemm_f16<<<dim3(8, 16), 256, SMEM_F>>>(ath, woth, out, DM, DM, 1,
                                           nullptr, nullptr, nullptr, nullptr, nullptr);
}

// round 15
// speedup vs baseline: 1.0019x; 1.0019x over previous
#include <cuda_runtime.h>
#include <cuda_fp16.h>
#include <cstdint>

#define SEQ 2048
#define DM 1024
#define NH 16
#define HD 64
#define NANCH 3
#define QPB 2

// ---------------- scratch ------------------------------------------------------
__device__ __half g_qh16[SEQ * DM];          // Q after RoPE, fp16 [S, H*D]
__device__ __half g_khh[NH * SEQ * HD];      // K after RoPE, fp16 [H,S,D] (128B rows)
__device__ __half g_vhh[NH * SEQ * HD];      // V fp16 [H,S,D] (128B rows)
__device__ __half g_xh[SEQ * DM];            // x fp16
__device__ __half g_wth[3072 * DM];          // [n,k] Wq|Wk|Wv^T fp16
__device__ __half g_woth[DM * DM];           // [n,k] Wo^T fp16
__device__ __half g_ath[SEQ * DM];           // attn out fp16 [S, H*D]

// ---------------- PTX helpers --------------------------------------------------
__device__ __forceinline__ uint32_t smem_u32(const void* p) {
    uint32_t a;
    asm("{ .reg .u64 t; cvta.to.shared.u64 t, %1; cvt.u32.u64 %0, t; }" : "=r"(a) : "l"(p));
    return a;
}
__device__ __forceinline__ void cp16(uint32_t s, const void* g) {
    asm volatile("cp.async.cg.shared.global [%0], [%1], 16;" :: "r"(s), "l"(g));
}
#define CP_COMMIT() asm volatile("cp.async.commit_group;" ::: "memory")
#define CP_WAIT2()  asm volatile("cp.async.wait_group 2;" ::: "memory")
#define CP_WAIT1()  asm volatile("cp.async.wait_group 1;" ::: "memory")
#define CP_WAIT0()  asm volatile("cp.async.wait_group 0;" ::: "memory")

__device__ __forceinline__ void ldsm_x4(uint32_t& r0, uint32_t& r1, uint32_t& r2,
                                        uint32_t& r3, uint32_t a) {
    asm volatile("ldmatrix.sync.aligned.m8n8.x4.shared.b16 {%0,%1,%2,%3}, [%4];"
                 : "=r"(r0), "=r"(r1), "=r"(r2), "=r"(r3) : "r"(a));
}
__device__ __forceinline__ void ldsm_x4_t(uint32_t& r0, uint32_t& r1, uint32_t& r2,
                                          uint32_t& r3, uint32_t a) {
    asm volatile("ldmatrix.sync.aligned.m8n8.x4.trans.shared.b16 {%0,%1,%2,%3}, [%4];"
                 : "=r"(r0), "=r"(r1), "=r"(r2), "=r"(r3) : "r"(a));
}
__device__ __forceinline__ void mma_f16(float* d, const uint32_t* a, const uint32_t* b) {
    asm volatile(
        "mma.sync.aligned.m16n8k16.row.col.f32.f16.f16.f32 "
        "{%0,%1,%2,%3}, {%4,%5,%6,%7}, {%8,%9}, {%0,%1,%2,%3};"
        : "+f"(d[0]), "+f"(d[1]), "+f"(d[2]), "+f"(d[3])
        : "r"(a[0]), "r"(a[1]), "r"(a[2]), "r"(a[3]), "r"(b[0]), "r"(b[1]));
}

// ---------------- prep -----------------------------------------------------------
__global__ void split_x(const float* __restrict__ x) {
    int i = blockIdx.x * 256 + threadIdx.x;
    const float4 v = ((const float4*)x)[i];
    __half2* o = (__half2*)(g_xh + 4 * (size_t)i);
    o[0] = __floats2half2_rn(v.x, v.y);
    o[1] = __floats2half2_rn(v.z, v.w);
}

// W [k][n] -> Wt [n][k] fp16. z 0..2 -> Wq/Wk/Wv; z==3 -> Wo
__global__ void transpose_w(const float* __restrict__ Wq, const float* __restrict__ Wk,
                            const float* __restrict__ Wv, const float* __restrict__ Wo) {
    __shared__ float tile[32][33];
    int z = blockIdx.z;
    const float* W = (z == 0) ? Wq : (z == 1) ? Wk : (z == 2) ? Wv : Wo;
    __half* dst = (z < 3) ? (g_wth + (size_t)z * DM * DM) : g_woth;
    int k0 = blockIdx.y * 32, n0 = blockIdx.x * 32;
    int tx = threadIdx.x, ty = threadIdx.y;
    tile[ty][tx] = W[(size_t)(k0 + ty) * DM + n0 + tx];
    __syncthreads();
    dst[(size_t)(n0 + ty) * DM + k0 + tx] = __float2half(tile[tx][ty]);
}

// ---------------- fp16 GEMM: C[M,N] = A[M,K] @ B[N,K]^T --------------------------
#define F_BK 64
#define F_STG 32768
#define F_OFF_B 16384
#define F_NSTAGE 4

__device__ __forceinline__ uint32_t swz8(uint32_t row, uint32_t seg) {
    return row * 128 + ((seg ^ (row & 7)) << 4);
}

__device__ __forceinline__ void f16_load_chunk(
    uint32_t stage, int tid, int c, int m0, int n0, int K,
    const __half* A, const __half* B)
{
    #pragma unroll
    for (int mtx = 0; mtx < 2; mtx++) {
        const int r0 = (mtx == 0) ? m0 : n0;
        const __half* src = (mtx == 0) ? A : B;
        const uint32_t off = mtx ? F_OFF_B : 0;
        #pragma unroll
        for (int i = 0; i < 4; i++) {
            int lin = i * 256 + tid;
            int row = lin >> 3, seg = lin & 7;
            const void* g = src + (size_t)(r0 + row) * K + c * F_BK + seg * 8;
            cp16(stage + off + swz8(row, seg), g);
        }
    }
}

__global__ void __launch_bounds__(256) gemm_f16(
    const __half* __restrict__ A, const __half* __restrict__ B,
    float* __restrict__ C, int Nstride, int K, int mode,
    __half* __restrict__ Qout, __half* __restrict__ Kout, __half* __restrict__ Vout,
    const float* __restrict__ cosT, const float* __restrict__ sinT)
{
    extern __shared__ __align__(1024) char dsm[];
    const uint32_t tiles = smem_u32(dsm);

    const int tid = threadIdx.x;
    const int m0 = blockIdx.y * 128, n0 = blockIdx.x * 128;
    const int nCh = K / F_BK;

    const int w = tid >> 5, lane = tid & 31;
    const int wm = (w & 3) * 32;
    const int wn = (w >> 2) * 64;

    float acc[2][8][4];
    #pragma unroll
    for (int i = 0; i < 2; i++)
        #pragma unroll
        for (int j = 0; j < 8; j++)
            #pragma unroll
            for (int e = 0; e < 4; e++) acc[i][j][e] = 0.f;

    f16_load_chunk(tiles, tid, 0, m0, n0, K, A, B); CP_COMMIT();
    f16_load_chunk(tiles + F_STG, tid, 1, m0, n0, K, A, B); CP_COMMIT();
    f16_load_chunk(tiles + 2 * F_STG, tid, 2, m0, n0, K, A, B); CP_COMMIT();

    const int aRowL = lane & 15;
    const int aSegL = lane >> 4;
    const int bRowL = ((lane >> 4) & 1) * 8 + (lane & 7);
    const int bSegL = (lane >> 3) & 1;

    for (int c = 0; c < nCh; c++) {
        const uint32_t buf = tiles + (c % F_NSTAGE) * F_STG;
        CP_WAIT2();
        __syncthreads();
        if (c + 3 < nCh)
            f16_load_chunk(tiles + ((c + 3) % F_NSTAGE) * F_STG, tid, c + 3, m0, n0, K, A, B);
        CP_COMMIT();

        #pragma unroll
        for (int k16 = 0; k16 < 4; k16++) {
            uint32_t af[2][4], bf[4][4];
            #pragma unroll
            for (int mt = 0; mt < 2; mt++) {
                uint32_t row = wm + mt * 16 + aRowL;
                ldsm_x4(af[mt][0], af[mt][1], af[mt][2], af[mt][3],
                        buf + swz8(row, k16 * 2 + aSegL));
            }
            #pragma unroll
            for (int np = 0; np < 4; np++) {
                uint32_t row = wn + np * 16 + bRowL;
                ldsm_x4(bf[np][0], bf[np][1], bf[np][2], bf[np][3],
                        buf + F_OFF_B + swz8(row, k16 * 2 + bSegL));
            }
            #pragma unroll
            for (int mt = 0; mt < 2; mt++)
                #pragma unroll
                for (int np = 0; np < 4; np++)
                    #pragma unroll
                    for (int h = 0; h < 2; h++)
                        mma_f16(acc[mt][np * 2 + h], af[mt], &bf[np][h * 2]);
        }
        __syncthreads();
    }

    const int erow = lane >> 2, ecol = (lane & 3) * 2;

    if (mode == 0) {
        const int ncol = n0 + wn;
        const int zsel = ncol >> 10;
        const int hh = (ncol >> 6) & 15;
        #pragma unroll
        for (int mt = 0; mt < 2; mt++) {
            #pragma unroll
            for (int rsel = 0; rsel < 2; rsel++) {
                const int s = m0 + wm + mt * 16 + erow + rsel * 8;
                if (zsel == 2) {
                    __half* vb = Vout + ((size_t)hh * SEQ + s) * HD;
                    #pragma unroll
                    for (int nt = 0; nt < 8; nt++)
                        *(__half2*)(vb + nt * 8 + ecol) =
                            __floats2half2_rn(acc[mt][nt][rsel * 2], acc[mt][nt][rsel * 2 + 1]);
                } else {
                    __half* ob = (zsel == 0) ? (Qout + (size_t)s * DM + hh * HD)
                                             : (Kout + ((size_t)hh * SEQ + s) * HD);
                    #pragma unroll
                    for (int nt = 0; nt < 4; nt++) {
                        const int d0 = nt * 8 + ecol;
                        const float c0 = cosT[s * 32 + d0],     sn0 = sinT[s * 32 + d0];
                        const float c1 = cosT[s * 32 + d0 + 1], sn1 = sinT[s * 32 + d0 + 1];
                        const float a0 = acc[mt][nt][rsel * 2],     a1 = acc[mt][nt][rsel * 2 + 1];
                        const float b0 = acc[mt][nt + 4][rsel * 2], b1 = acc[mt][nt + 4][rsel * 2 + 1];
                        *(__half2*)(ob + d0) =
                            __floats2half2_rn(a0 * c0 - b0 * sn0, a1 * c1 - b1 * sn1);
                        *(__half2*)(ob + d0 + 32) =
                            __floats2half2_rn(b0 * c0 + a0 * sn0, b1 * c1 + a1 * sn1);
                    }
                }
            }
        }
    } else {
        #pragma unroll
        for (int mt = 0; mt < 2; mt++)
            #pragma unroll
            for (int nt = 0; nt < 8; nt++) {
                const float* d = acc[mt][nt];
                size_t r = (size_t)(m0 + wm + mt * 16 + erow);
                size_t col = n0 + wn + nt * 8 + ecol;
                *(float2*)&C[r * Nstride + col]       = make_float2(d[0], d[1]);
                *(float2*)&C[(r + 8) * Nstride + col] = make_float2(d[2], d[3]);
            }
    }
}

// ---------------- sparse attention -----------------------------------------------
// 2 queries / 256-thread block, 4 warps per query. QK^T and P*V on mma.sync.
// Dynamic smem (per block):
//   [ql*16384 +    0 .. 8192)  K tiles (4 x 16 x 128B, swizzled)
//   [ql*16384 + 8192 ..16384)  V tiles (same layout)
//   32768: sqh, 33280: sw16, 33536: stile, 33568: wred, 33632: spart
#define ATTN_SMEM 35712

__global__ void __launch_bounds__(256) attn(const int* __restrict__ anchors) {
    extern __shared__ __align__(128) char dyn[];
    const int h = blockIdx.y;
    const int tid = threadIdx.x;
    const int ql = tid >> 7;                 // query in block (0..1)
    const int jq = tid & 127;                // thread within query
    const int s = blockIdx.x * QPB + ql;
    const int wq = (tid >> 5) & 3;           // warp within query (0..3)
    const int lane = tid & 31;
    const int tig = lane & 3;

    __half2* sqh  = (__half2*)(dyn + 32768) + ql * 32;
    __half*  sw16 = (__half*)(dyn + 33280) + ql * 64;
    int*     stile = (int*)(dyn + 33536) + ql * 4;
    float*   wred = (float*)(dyn + 33568) + ql * 8;    // [0..3]=max, [4..7]=sum
    float*   spart = (float*)(dyn + 33632) + ql * 256; // [wq*64 + dim]

    // q (half2) and tile indices
    if (jq < 32)
        sqh[jq] = ((const __half2*)(g_qh16 + (size_t)s * DM + h * HD))[jq];
    if (jq < 4)
        stile[jq] = (jq < NANCH) ? anchors[(h * SEQ + s) * NANCH + jq] : (s >> 4);
    __syncthreads();

    const int t0 = stile[0], t1 = stile[1], t2 = stile[2], t3 = stile[3];

    // stage K tiles (group A) then V tiles (group B); 128 threads/query,
    // thread jq stages 16B chunk jq of each tile. Swizzle key = row & 7.
    const uint32_t sbase = smem_u32(dyn) + ql * 16384;
    {
        const uint32_t so = (jq >> 3) * 128 + (((jq & 7) ^ ((jq >> 3) & 7)) << 4);
        const uint32_t go = jq * 16;
        const char* kb0 = (const char*)g_khh + (size_t)h * SEQ * 128 + go;
        cp16(sbase + so,        kb0 + t0 * 2048);
        cp16(sbase + 2048 + so, kb0 + t1 * 2048);
        cp16(sbase + 4096 + so, kb0 + t2 * 2048);
        cp16(sbase + 6144 + so, kb0 + t3 * 2048);
        CP_COMMIT();
        const char* vb0 = (const char*)g_vhh + (size_t)h * SEQ * 128 + go;
        const uint32_t sv = sbase + 8192;
        cp16(sv + so,        vb0 + t0 * 2048);
        cp16(sv + 2048 + so, vb0 + t1 * 2048);
        cp16(sv + 4096 + so, vb0 + t2 * 2048);
        cp16(sv + 6144 + so, vb0 + t3 * 2048);
        CP_COMMIT();
    }
    CP_WAIT1();          // K tiles ready (V still in flight)
    __syncthreads();

    // B fragments: q replicated across all 8 n-columns
    uint32_t bq[4][2];
    #pragma unroll
    for (int c = 0; c < 4; c++) {
        bq[c][0] = *(const uint32_t*)&sqh[c * 8 + tig];
        bq[c][1] = *(const uint32_t*)&sqh[c * 8 + tig + 4];
    }

    // logits via mma: warp wq owns m-tile of 16 keys (rows wq*16..+15)
    float lg[2];
    {
        float c4[4] = {0.f, 0.f, 0.f, 0.f};
        #pragma unroll
        for (int c = 0; c < 4; c++) {
            uint32_t a[4];
            ldsm_x4(a[0], a[1], a[2], a[3],
                    sbase + swz8(wq * 16 + (lane & 15), c * 2 + (lane >> 4)));
            mma_f16(c4, a, bq[c]);
        }
        lg[0] = c4[0] * 0.125f;              // key wq*16 + r
        lg[1] = c4[2] * 0.125f;              // key wq*16 + 8 + r
    }

    CP_WAIT0();          // V tiles ready (visibility sealed by syncthreads below)

    const int r = lane >> 2;
    const int tw = (wq == 0) ? t0 : (wq == 1) ? t1 : (wq == 2) ? t2 : t3;
    const int kid0 = tw * 16 + r, kid1 = tw * 16 + 8 + r;
    const bool m0b = kid0 > s, m1b = kid1 > s;
    if (m0b) lg[0] = -1e30f;
    if (m1b) lg[1] = -1e30f;

    // softmax (each key duplicated x4 across the quad -> sum scaled by 0.25)
    float m = fmaxf(lg[0], lg[1]);
    #pragma unroll
    for (int off = 16; off; off >>= 1) m = fmaxf(m, __shfl_xor_sync(~0u, m, off));
    if (lane == 0) wred[wq] = m;
    __syncthreads();
    m = fmaxf(fmaxf(wred[0], wred[1]), fmaxf(wred[2], wred[3]));

    const float e0 = m0b ? 0.f : __expf(lg[0] - m);
    const float e1 = m1b ? 0.f : __expf(lg[1] - m);
    float lsum = e0 + e1;
    #pragma unroll
    for (int off = 16; off; off >>= 1) lsum += __shfl_xor_sync(~0u, lsum, off);
    if (lane == 0) wred[4 + wq] = lsum;
    __syncthreads();
    const float inv = 4.0f / (wred[4] + wred[5] + wred[6] + wred[7]);

    // quad leaders publish fp16 weights
    if (tig == 0) {
        sw16[wq * 16 + r]     = __float2half(e0 * inv);
        sw16[wq * 16 + 8 + r] = __float2half(e1 * inv);
    }
    __syncwarp();

    // P*V via mma: warp wq's 16 keys (1 k-chunk) x 64 dims (4 m-tiles).
    // A = V^T via ldmatrix.trans; B = weights replicated over n.
    {
        const uint32_t sVb = sbase + 8192;
        const int kb = wq * 16;
        uint32_t bw[2];
        bw[0] = *(const uint32_t*)&sw16[kb + 2 * tig];
        bw[1] = *(const uint32_t*)&sw16[kb + 8 + 2 * tig];
        const int g = lane >> 3;
        const int row = kb + (lane & 7) + ((g & 2) << 2);
        const int segadd = g & 1;
        const uint32_t rowoff = row * 128;
        const uint32_t rx = (row & 7);
        #pragma unroll
        for (int mt = 0; mt < 4; mt++) {
            float c4[4] = {0.f, 0.f, 0.f, 0.f};
            uint32_t a[4];
            const uint32_t seg = 2 * mt + segadd;
            ldsm_x4_t(a[0], a[1], a[2], a[3], sVb + rowoff + ((seg ^ rx) << 4));
            mma_f16(c4, a, bw);
            if (tig == 0) {
                spart[wq * 64 + mt * 16 + r]     = c4[0];
                spart[wq * 64 + mt * 16 + 8 + r] = c4[2];
            }
        }
    }
    __syncthreads();

    if (jq < 64)
        g_ath[(size_t)s * DM + h * HD + jq] =
            __float2half(spart[jq] + spart[64 + jq] + spart[128 + jq] + spart[192 + jq]);
}

// ---------------- launch ---------------------------------------------------------
extern "C" void kernel_launch(void* const* d_in, const int* in_sizes, int n_in,
                              void* d_out, int out_size)
{
    const float* x    = (const float*)d_in[0];
    const float* Wq   = (const float*)d_in[1];
    const float* Wk   = (const float*)d_in[2];
    const float* Wv   = (const float*)d_in[3];
    const float* Wo   = (const float*)d_in[4];
    const float* cosT = (const float*)d_in[5];
    const float* sinT = (const float*)d_in[6];
    const int* anchors = (const int*)d_in[7];
    float* out = (float*)d_out;

    const int SMEM_F = F_NSTAGE * F_STG;   // 128 KB
    cudaFuncSetAttribute(gemm_f16, cudaFuncAttributeMaxDynamicSharedMemorySize, SMEM_F);
    cudaFuncSetAttribute(attn, cudaFuncAttributeMaxDynamicSharedMemorySize, ATTN_SMEM);

    __half *xh = nullptr, *wth = nullptr, *woth = nullptr, *ath = nullptr;
    __half *qh = nullptr, *kh = nullptr, *vh = nullptr;
    cudaGetSymbolAddress((void**)&xh, g_xh);
    cudaGetSymbolAddress((void**)&wth, g_wth);
    cudaGetSymbolAddress((void**)&woth, g_woth);
    cudaGetSymbolAddress((void**)&ath, g_ath);
    cudaGetSymbolAddress((void**)&qh, g_qh16);
    cudaGetSymbolAddress((void**)&kh, g_khh);
    cudaGetSymbolAddress((void**)&vh, g_vhh);

    split_x<<<(SEQ * DM / 4) / 256, 256>>>(x);
    transpose_w<<<dim3(32, 32, 4), dim3(32, 32)>>>(Wq, Wk, Wv, Wo);

    // QKV GEMM with fused RoPE/split/fp16 epilogue
    gemm_f16<<<dim3(24, 16), 256, SMEM_F>>>(xh, wth, nullptr, 3072, DM, 0,
                                            qh, kh, vh, cosT, sinT);

    attn<<<dim3(SEQ / QPB, NH), 256, ATTN_SMEM>>>(anchors);

    // out = att @ Wo (plain fp32 epilogue)
    gemm_f16<<<dim3(8, 16), 256, SMEM_F>>>(ath, woth, out, DM, DM, 1,
                                           nullptr, nullptr, nullptr, nullptr, nullptr);
}

// round 16
// speedup vs baseline: 1.0352x; 1.0332x over previous
#include <cuda_runtime.h>
#include <cuda_fp16.h>
#include <cstdint>

#define SEQ 2048
#define DM 1024
#define NH 16
#define HD 64
#define NANCH 3
#define QPB 4

// ---------------- scratch ------------------------------------------------------
__device__ __half g_qh16[SEQ * DM];          // Q after RoPE, fp16 [S, H*D]
__device__ __half g_khh[NH * SEQ * HD];      // K after RoPE, fp16 [H,S,D] (128B rows)
__device__ __half g_vhh[NH * SEQ * HD];      // V fp16 [H,S,D] (128B rows)
__device__ __half g_xh[SEQ * DM];            // x fp16
__device__ __half g_wth[3072 * DM];          // [n,k] Wq|Wk|Wv^T fp16
__device__ __half g_woth[DM * DM];           // [n,k] Wo^T fp16
__device__ __half g_ath[SEQ * DM];           // attn out fp16 [S, H*D]

// ---------------- PTX helpers --------------------------------------------------
__device__ __forceinline__ uint32_t smem_u32(const void* p) {
    uint32_t a;
    asm("{ .reg .u64 t; cvta.to.shared.u64 t, %1; cvt.u32.u64 %0, t; }" : "=r"(a) : "l"(p));
    return a;
}
__device__ __forceinline__ void cp16(uint32_t s, const void* g) {
    asm volatile("cp.async.cg.shared.global [%0], [%1], 16;" :: "r"(s), "l"(g));
}
#define CP_COMMIT() asm volatile("cp.async.commit_group;" ::: "memory")
#define CP_WAIT2()  asm volatile("cp.async.wait_group 2;" ::: "memory")
#define CP_WAIT0()  asm volatile("cp.async.wait_group 0;" ::: "memory")

__device__ __forceinline__ void ldsm_x4(uint32_t& r0, uint32_t& r1, uint32_t& r2,
                                        uint32_t& r3, uint32_t a) {
    asm volatile("ldmatrix.sync.aligned.m8n8.x4.shared.b16 {%0,%1,%2,%3}, [%4];"
                 : "=r"(r0), "=r"(r1), "=r"(r2), "=r"(r3) : "r"(a));
}
__device__ __forceinline__ void mma_f16(float* d, const uint32_t* a, const uint32_t* b) {
    asm volatile(
        "mma.sync.aligned.m16n8k16.row.col.f32.f16.f16.f32 "
        "{%0,%1,%2,%3}, {%4,%5,%6,%7}, {%8,%9}, {%0,%1,%2,%3};"
        : "+f"(d[0]), "+f"(d[1]), "+f"(d[2]), "+f"(d[3])
        : "r"(a[0]), "r"(a[1]), "r"(a[2]), "r"(a[3]), "r"(b[0]), "r"(b[1]));
}

// ---------------- prep -----------------------------------------------------------
__global__ void split_x(const float* __restrict__ x) {
    int i = blockIdx.x * 256 + threadIdx.x;
    const float4 v = ((const float4*)x)[i];
    __half2* o = (__half2*)(g_xh + 4 * (size_t)i);
    o[0] = __floats2half2_rn(v.x, v.y);
    o[1] = __floats2half2_rn(v.z, v.w);
}

// W [k][n] -> Wt [n][k] fp16. z 0..2 -> Wq/Wk/Wv; z==3 -> Wo
__global__ void transpose_w(const float* __restrict__ Wq, const float* __restrict__ Wk,
                            const float* __restrict__ Wv, const float* __restrict__ Wo) {
    __shared__ float tile[32][33];
    int z = blockIdx.z;
    const float* W = (z == 0) ? Wq : (z == 1) ? Wk : (z == 2) ? Wv : Wo;
    __half* dst = (z < 3) ? (g_wth + (size_t)z * DM * DM) : g_woth;
    int k0 = blockIdx.y * 32, n0 = blockIdx.x * 32;
    int tx = threadIdx.x, ty = threadIdx.y;
    tile[ty][tx] = W[(size_t)(k0 + ty) * DM + n0 + tx];
    __syncthreads();
    dst[(size_t)(n0 + ty) * DM + k0 + tx] = __float2half(tile[tx][ty]);
}

// ---------------- fp16 GEMM: C[M,N] = A[M,K] @ B[N,K]^T --------------------------
// 128x128x64 CTA tile, 8 warps (4m x 2n), 4-stage cp.async pipeline.
#define F_BK 64
#define F_STG 32768
#define F_OFF_B 16384
#define F_NSTAGE 4

__device__ __forceinline__ uint32_t swz8(uint32_t row, uint32_t seg) {
    return row * 128 + ((seg ^ (row & 7)) << 4);
}

__device__ __forceinline__ void f16_load_chunk(
    uint32_t stage, int tid, int c, int m0, int n0, int K,
    const __half* A, const __half* B)
{
    #pragma unroll
    for (int mtx = 0; mtx < 2; mtx++) {
        const int r0 = (mtx == 0) ? m0 : n0;
        const __half* src = (mtx == 0) ? A : B;
        const uint32_t off = mtx ? F_OFF_B : 0;
        #pragma unroll
        for (int i = 0; i < 4; i++) {
            int lin = i * 256 + tid;
            int row = lin >> 3, seg = lin & 7;
            const void* g = src + (size_t)(r0 + row) * K + c * F_BK + seg * 8;
            cp16(stage + off + swz8(row, seg), g);
        }
    }
}

__global__ void __launch_bounds__(256) gemm_f16(
    const __half* __restrict__ A, const __half* __restrict__ B,
    float* __restrict__ C, int Nstride, int K, int mode,
    __half* __restrict__ Qout, __half* __restrict__ Kout, __half* __restrict__ Vout,
    const float* __restrict__ cosT, const float* __restrict__ sinT)
{
    extern __shared__ __align__(1024) char dsm[];
    const uint32_t tiles = smem_u32(dsm);

    const int tid = threadIdx.x;
    const int m0 = blockIdx.y * 128, n0 = blockIdx.x * 128;
    const int nCh = K / F_BK;

    const int w = tid >> 5, lane = tid & 31;
    const int wm = (w & 3) * 32;
    const int wn = (w >> 2) * 64;

    float acc[2][8][4];
    #pragma unroll
    for (int i = 0; i < 2; i++)
        #pragma unroll
        for (int j = 0; j < 8; j++)
            #pragma unroll
            for (int e = 0; e < 4; e++) acc[i][j][e] = 0.f;

    f16_load_chunk(tiles, tid, 0, m0, n0, K, A, B); CP_COMMIT();
    f16_load_chunk(tiles + F_STG, tid, 1, m0, n0, K, A, B); CP_COMMIT();
    f16_load_chunk(tiles + 2 * F_STG, tid, 2, m0, n0, K, A, B); CP_COMMIT();

    const int aRowL = lane & 15;
    const int aSegL = lane >> 4;
    const int bRowL = ((lane >> 4) & 1) * 8 + (lane & 7);
    const int bSegL = (lane >> 3) & 1;

    for (int c = 0; c < nCh; c++) {
        const uint32_t buf = tiles + (c % F_NSTAGE) * F_STG;
        CP_WAIT2();
        __syncthreads();
        if (c + 3 < nCh)
            f16_load_chunk(tiles + ((c + 3) % F_NSTAGE) * F_STG, tid, c + 3, m0, n0, K, A, B);
        CP_COMMIT();

        #pragma unroll
        for (int k16 = 0; k16 < 4; k16++) {
            uint32_t af[2][4], bf[4][4];
            #pragma unroll
            for (int mt = 0; mt < 2; mt++) {
                uint32_t row = wm + mt * 16 + aRowL;
                ldsm_x4(af[mt][0], af[mt][1], af[mt][2], af[mt][3],
                        buf + swz8(row, k16 * 2 + aSegL));
            }
            #pragma unroll
            for (int np = 0; np < 4; np++) {
                uint32_t row = wn + np * 16 + bRowL;
                ldsm_x4(bf[np][0], bf[np][1], bf[np][2], bf[np][3],
                        buf + F_OFF_B + swz8(row, k16 * 2 + bSegL));
            }
            #pragma unroll
            for (int mt = 0; mt < 2; mt++)
                #pragma unroll
                for (int np = 0; np < 4; np++)
                    #pragma unroll
                    for (int h = 0; h < 2; h++)
                        mma_f16(acc[mt][np * 2 + h], af[mt], &bf[np][h * 2]);
        }
        __syncthreads();
    }

    const int erow = lane >> 2, ecol = (lane & 3) * 2;

    if (mode == 0) {
        const int ncol = n0 + wn;
        const int zsel = ncol >> 10;
        const int hh = (ncol >> 6) & 15;
        #pragma unroll
        for (int mt = 0; mt < 2; mt++) {
            #pragma unroll
            for (int rsel = 0; rsel < 2; rsel++) {
                const int s = m0 + wm + mt * 16 + erow + rsel * 8;
                if (zsel == 2) {
                    __half* vb = Vout + ((size_t)hh * SEQ + s) * HD;
                    #pragma unroll
                    for (int nt = 0; nt < 8; nt++)
                        *(__half2*)(vb + nt * 8 + ecol) =
                            __floats2half2_rn(acc[mt][nt][rsel * 2], acc[mt][nt][rsel * 2 + 1]);
                } else {
                    __half* ob = (zsel == 0) ? (Qout + (size_t)s * DM + hh * HD)
                                             : (Kout + ((size_t)hh * SEQ + s) * HD);
                    #pragma unroll
                    for (int nt = 0; nt < 4; nt++) {
                        const int d0 = nt * 8 + ecol;
                        const float c0 = cosT[s * 32 + d0],     sn0 = sinT[s * 32 + d0];
                        const float c1 = cosT[s * 32 + d0 + 1], sn1 = sinT[s * 32 + d0 + 1];
                        const float a0 = acc[mt][nt][rsel * 2],     a1 = acc[mt][nt][rsel * 2 + 1];
                        const float b0 = acc[mt][nt + 4][rsel * 2], b1 = acc[mt][nt + 4][rsel * 2 + 1];
                        *(__half2*)(ob + d0) =
                            __floats2half2_rn(a0 * c0 - b0 * sn0, a1 * c1 - b1 * sn1);
                        *(__half2*)(ob + d0 + 32) =
                            __floats2half2_rn(b0 * c0 + a0 * sn0, b1 * c1 + a1 * sn1);
                    }
                }
            }
        }
    } else {
        #pragma unroll
        for (int mt = 0; mt < 2; mt++)
            #pragma unroll
            for (int nt = 0; nt < 8; nt++) {
                const float* d = acc[mt][nt];
                size_t r = (size_t)(m0 + wm + mt * 16 + erow);
                size_t col = n0 + wn + nt * 8 + ecol;
                *(float2*)&C[r * Nstride + col]       = make_float2(d[0], d[1]);
                *(float2*)&C[(r + 8) * Nstride + col] = make_float2(d[2], d[3]);
            }
    }
}

// ---------------- sparse attention: 4 queries / 256-thread block ----------------
// Logits via mma.sync; V phase scalar with shuffle-fed weights (best measured).
__global__ void __launch_bounds__(256) attn(const int* __restrict__ anchors) {
    const int h = blockIdx.y;
    const int tid = threadIdx.x;
    const int ql = tid >> 6;
    const int j = tid & 63;
    const int s = blockIdx.x * QPB + ql;
    const int wq = (tid >> 5) & 1;
    const int lane = tid & 31;
    const int tig = lane & 3;

    __shared__ __align__(16) char sK[QPB][4 * 2048];   // 4 tiles x 16 rows x 128B
    __shared__ __half2 sqh[QPB][32];                   // q as half2
    __shared__ float2 sWO[QPB][64];                    // (weight, byteoff-as-float)
    __shared__ int stile[QPB][4];
    __shared__ float wred[QPB][2][2];
    __shared__ float spart[QPB][2][64];

    // q (half2) and tile indices
    if (j < 32)
        sqh[ql][j] = ((const __half2*)(g_qh16 + (size_t)s * DM + h * HD))[j];
    if (j < 4)
        stile[ql][j] = (j < NANCH) ? anchors[(h * SEQ + s) * NANCH + j] : (s >> 4);
    __syncthreads();

    const int t0 = stile[ql][0], t1 = stile[ql][1];
    const int t2 = stile[ql][2], t3 = stile[ql][3];

    // stage 4 K tiles (2KB each, contiguous) with invariant per-thread offsets
    {
        const uint32_t sbase = smem_u32(sK[ql]);
        const char* hb = (const char*)g_khh + (size_t)h * SEQ * 128;
        const uint32_t so = (j >> 3) * 128 + (((j & 7) ^ (j >> 3)) << 4);
        const uint32_t go = j * 16;
        const char* p0 = hb + t0 * 2048 + go;
        const char* p1 = hb + t1 * 2048 + go;
        const char* p2 = hb + t2 * 2048 + go;
        const char* p3 = hb + t3 * 2048 + go;
        cp16(sbase + so,        p0);
        cp16(sbase + 1024 + so, p0 + 1024);
        cp16(sbase + 2048 + so, p1);
        cp16(sbase + 3072 + so, p1 + 1024);
        cp16(sbase + 4096 + so, p2);
        cp16(sbase + 5120 + so, p2 + 1024);
        cp16(sbase + 6144 + so, p3);
        cp16(sbase + 7168 + so, p3 + 1024);
    }
    CP_COMMIT();
    CP_WAIT0();
    __syncthreads();

    // B fragments: q replicated across all 8 n-columns
    uint32_t bq[4][2];
    #pragma unroll
    for (int c = 0; c < 4; c++) {
        bq[c][0] = *(const uint32_t*)&sqh[ql][c * 8 + tig];
        bq[c][1] = *(const uint32_t*)&sqh[ql][c * 8 + tig + 4];
    }

    // logits via mma: 2 m-tiles of 16 keys, 4 k-chunks each
    const uint32_t sKb = smem_u32(sK[ql]);
    float lg[4];                             // keys: wq*32 + {r, r+8, 16+r, 24+r}
    #pragma unroll
    for (int t = 0; t < 2; t++) {
        float c4[4] = {0.f, 0.f, 0.f, 0.f};
        #pragma unroll
        for (int c = 0; c < 4; c++) {
            uint32_t a[4];
            ldsm_x4(a[0], a[1], a[2], a[3],
                    sKb + swz8(wq * 32 + t * 16 + (lane & 15), c * 2 + (lane >> 4)));
            mma_f16(c4, a, bq[c]);
        }
        lg[t * 2]     = c4[0] * 0.125f;
        lg[t * 2 + 1] = c4[2] * 0.125f;
    }

    const int r = lane >> 2;
    const int ti0 = wq ? t2 : t0, ti1 = wq ? t3 : t1;
    int kid[4] = {ti0 * 16 + r, ti0 * 16 + r + 8, ti1 * 16 + r, ti1 * 16 + r + 8};
    bool msk[4];
    #pragma unroll
    for (int i = 0; i < 4; i++) {
        msk[i] = kid[i] > s;
        if (msk[i]) lg[i] = -1e30f;
    }

    // softmax (each key duplicated x4 across the quad -> sum scaled by 0.25)
    float m = fmaxf(fmaxf(lg[0], lg[1]), fmaxf(lg[2], lg[3]));
    #pragma unroll
    for (int off = 16; off; off >>= 1) m = fmaxf(m, __shfl_xor_sync(~0u, m, off));
    if (lane == 0) wred[ql][0][wq] = m;
    __syncthreads();
    m = fmaxf(wred[ql][0][0], wred[ql][0][1]);

    float e[4];
    float lsum = 0.f;
    #pragma unroll
    for (int i = 0; i < 4; i++) {
        e[i] = msk[i] ? 0.f : __expf(lg[i] - m);
        lsum += e[i];
    }
    #pragma unroll
    for (int off = 16; off; off >>= 1) lsum += __shfl_xor_sync(~0u, lsum, off);
    if (lane == 0) wred[ql][1][wq] = lsum;
    __syncthreads();
    const float inv = 4.0f / (wred[ql][1][0] + wred[ql][1][1]);

    // quad leaders publish (weight, V byte offset) for their 4 keys
    if (tig == 0) {
        sWO[ql][wq * 32 + r]      = make_float2(e[0] * inv, __int_as_float(kid[0] << 7));
        sWO[ql][wq * 32 + r + 8]  = make_float2(e[1] * inv, __int_as_float(kid[1] << 7));
        sWO[ql][wq * 32 + r + 16] = make_float2(e[2] * inv, __int_as_float(kid[2] << 7));
        sWO[ql][wq * 32 + r + 24] = make_float2(e[3] * inv, __int_as_float(kid[3] << 7));
    }
    __syncwarp();

    // V phase: 2 keys per iteration; lanes 0-15 even key, 16-31 odd key.
    {
        const char* vb = (const char*)g_vhh + (size_t)h * SEQ * 128 + 8 * (lane & 15);
        const int sel = lane >> 4;           // 0 or 1
        float4 acc = make_float4(0.f, 0.f, 0.f, 0.f);
        #pragma unroll
        for (int i = 0; i < 16; i++) {
            const float2 wo = sWO[ql][wq * 32 + 2 * i + sel];
            const float wgt = wo.x;
            const __half2* vp = (const __half2*)(vb + __float_as_int(wo.y));
            const float2 v0 = __half22float2(vp[0]);
            const float2 v1 = __half22float2(vp[1]);
            acc.x = fmaf(wgt, v0.x, acc.x);
            acc.y = fmaf(wgt, v0.y, acc.y);
            acc.z = fmaf(wgt, v1.x, acc.z);
            acc.w = fmaf(wgt, v1.y, acc.w);
        }
        acc.x += __shfl_xor_sync(~0u, acc.x, 16);
        acc.y += __shfl_xor_sync(~0u, acc.y, 16);
        acc.z += __shfl_xor_sync(~0u, acc.z, 16);
        acc.w += __shfl_xor_sync(~0u, acc.w, 16);
        if (lane < 16)
            ((float4*)spart[ql][wq])[lane] = acc;
    }
    __syncthreads();

    g_ath[(size_t)s * DM + h * HD + j] =
        __float2half(spart[ql][0][j] + spart[ql][1][j]);
}

// ---------------- launch ---------------------------------------------------------
extern "C" void kernel_launch(void* const* d_in, const int* in_sizes, int n_in,
                              void* d_out, int out_size)
{
    const float* x    = (const float*)d_in[0];
    const float* Wq   = (const float*)d_in[1];
    const float* Wk   = (const float*)d_in[2];
    const float* Wv   = (const float*)d_in[3];
    const float* Wo   = (const float*)d_in[4];
    const float* cosT = (const float*)d_in[5];
    const float* sinT = (const float*)d_in[6];
    const int* anchors = (const int*)d_in[7];
    float* out = (float*)d_out;

    const int SMEM_F = F_NSTAGE * F_STG;   // 128 KB
    cudaFuncSetAttribute(gemm_f16, cudaFuncAttributeMaxDynamicSharedMemorySize, SMEM_F);

    __half *xh = nullptr, *wth = nullptr, *woth = nullptr, *ath = nullptr;
    __half *qh = nullptr, *kh = nullptr, *vh = nullptr;
    cudaGetSymbolAddress((void**)&xh, g_xh);
    cudaGetSymbolAddress((void**)&wth, g_wth);
    cudaGetSymbolAddress((void**)&woth, g_woth);
    cudaGetSymbolAddress((void**)&ath, g_ath);
    cudaGetSymbolAddress((void**)&qh, g_qh16);
    cudaGetSymbolAddress((void**)&kh, g_khh);
    cudaGetSymbolAddress((void**)&vh, g_vhh);

    split_x<<<(SEQ * DM / 4) / 256, 256>>>(x);
    transpose_w<<<dim3(32, 32, 4), dim3(32, 32)>>>(Wq, Wk, Wv, Wo);

    // QKV GEMM with fused RoPE/split/fp16 epilogue
    gemm_f16<<<dim3(24, 16), 256, SMEM_F>>>(xh, wth, nullptr, 3072, DM, 0,
                                            qh, kh, vh, cosT, sinT);

    attn<<<dim3(SEQ / QPB, NH), 256>>>(anchors);

    // out = att @ Wo (plain fp32 epilogue)
    gemm_f16<<<dim3(8, 16), 256, SMEM_F>>>(ath, woth, out, DM, DM, 1,
                                           nullptr, nullptr, nullptr, nullptr, nullptr);
}

// round 17
// speedup vs baseline: 1.0886x; 1.0515x over previous
#include <cuda_runtime.h>
#include <cuda_fp16.h>
#include <cstdint>

#define SEQ 2048
#define DM 1024
#define NH 16
#define HD 64
#define NANCH 3
#define QPB 4

// ---------------- scratch ------------------------------------------------------
__device__ __half g_qh16[SEQ * DM];          // Q after RoPE, fp16 [S, H*D]
__device__ __half g_khh[NH * SEQ * HD];      // K after RoPE, fp16 [H,S,D] (128B rows)
__device__ __half g_vhh[NH * SEQ * HD];      // V fp16 [H,S,D] (128B rows)
__device__ __half g_xh[SEQ * DM];            // x fp16
__device__ __half g_wth[3072 * DM];          // [n,k] Wq|Wk|Wv^T fp16
__device__ __half g_woth[DM * DM];           // [n,k] Wo^T fp16
__device__ __half g_ath[SEQ * DM];           // attn out fp16 [S, H*D]

// ---------------- PTX helpers --------------------------------------------------
__device__ __forceinline__ uint32_t smem_u32(const void* p) {
    uint32_t a;
    asm("{ .reg .u64 t; cvta.to.shared.u64 t, %1; cvt.u32.u64 %0, t; }" : "=r"(a) : "l"(p));
    return a;
}
__device__ __forceinline__ void cp16(uint32_t s, const void* g) {
    asm volatile("cp.async.cg.shared.global [%0], [%1], 16;" :: "r"(s), "l"(g));
}
#define CP_COMMIT() asm volatile("cp.async.commit_group;" ::: "memory")
#define CP_WAIT2()  asm volatile("cp.async.wait_group 2;" ::: "memory")
#define CP_WAIT0()  asm volatile("cp.async.wait_group 0;" ::: "memory")

__device__ __forceinline__ void ldsm_x4(uint32_t& r0, uint32_t& r1, uint32_t& r2,
                                        uint32_t& r3, uint32_t a) {
    asm volatile("ldmatrix.sync.aligned.m8n8.x4.shared.b16 {%0,%1,%2,%3}, [%4];"
                 : "=r"(r0), "=r"(r1), "=r"(r2), "=r"(r3) : "r"(a));
}
__device__ __forceinline__ void mma_f16(float* d, const uint32_t* a, const uint32_t* b) {
    asm volatile(
        "mma.sync.aligned.m16n8k16.row.col.f32.f16.f16.f32 "
        "{%0,%1,%2,%3}, {%4,%5,%6,%7}, {%8,%9}, {%0,%1,%2,%3};"
        : "+f"(d[0]), "+f"(d[1]), "+f"(d[2]), "+f"(d[3])
        : "r"(a[0]), "r"(a[1]), "r"(a[2]), "r"(a[3]), "r"(b[0]), "r"(b[1]));
}

// ---------------- prep -----------------------------------------------------------
__global__ void split_x(const float* __restrict__ x) {
    int i = blockIdx.x * 256 + threadIdx.x;
    const float4 v = ((const float4*)x)[i];
    __half2* o = (__half2*)(g_xh + 4 * (size_t)i);
    o[0] = __floats2half2_rn(v.x, v.y);
    o[1] = __floats2half2_rn(v.z, v.w);
}

// W [k][n] -> Wt [n][k] fp16. z 0..2 -> Wq/Wk/Wv; z==3 -> Wo
__global__ void transpose_w(const float* __restrict__ Wq, const float* __restrict__ Wk,
                            const float* __restrict__ Wv, const float* __restrict__ Wo) {
    __shared__ float tile[32][33];
    int z = blockIdx.z;
    const float* W = (z == 0) ? Wq : (z == 1) ? Wk : (z == 2) ? Wv : Wo;
    __half* dst = (z < 3) ? (g_wth + (size_t)z * DM * DM) : g_woth;
    int k0 = blockIdx.y * 32, n0 = blockIdx.x * 32;
    int tx = threadIdx.x, ty = threadIdx.y;
    tile[ty][tx] = W[(size_t)(k0 + ty) * DM + n0 + tx];
    __syncthreads();
    dst[(size_t)(n0 + ty) * DM + k0 + tx] = __float2half(tile[tx][ty]);
}

// ---------------- fp16 GEMM: C[M,N] = A[M,K] @ B[N,K]^T --------------------------
// 128x128x64 CTA tile, 8 warps (4m x 2n), 4-stage cp.async pipeline.
#define F_BK 64
#define F_STG 32768
#define F_OFF_B 16384
#define F_NSTAGE 4

__device__ __forceinline__ uint32_t swz8(uint32_t row, uint32_t seg) {
    return row * 128 + ((seg ^ (row & 7)) << 4);
}

__device__ __forceinline__ void f16_load_chunk(
    uint32_t stage, int tid, int c, int m0, int n0, int K,
    const __half* A, const __half* B)
{
    #pragma unroll
    for (int mtx = 0; mtx < 2; mtx++) {
        const int r0 = (mtx == 0) ? m0 : n0;
        const __half* src = (mtx == 0) ? A : B;
        const uint32_t off = mtx ? F_OFF_B : 0;
        #pragma unroll
        for (int i = 0; i < 4; i++) {
            int lin = i * 256 + tid;
            int row = lin >> 3, seg = lin & 7;
            const void* g = src + (size_t)(r0 + row) * K + c * F_BK + seg * 8;
            cp16(stage + off + swz8(row, seg), g);
        }
    }
}

__global__ void __launch_bounds__(256) gemm_f16(
    const __half* __restrict__ A, const __half* __restrict__ B,
    float* __restrict__ C, int Nstride, int K, int mode,
    __half* __restrict__ Qout, __half* __restrict__ Kout, __half* __restrict__ Vout,
    const float* __restrict__ cosT, const float* __restrict__ sinT)
{
    extern __shared__ __align__(1024) char dsm[];
    const uint32_t tiles = smem_u32(dsm);

    const int tid = threadIdx.x;
    const int m0 = blockIdx.y * 128, n0 = blockIdx.x * 128;
    const int nCh = K / F_BK;

    const int w = tid >> 5, lane = tid & 31;
    const int wm = (w & 3) * 32;
    const int wn = (w >> 2) * 64;

    float acc[2][8][4];
    #pragma unroll
    for (int i = 0; i < 2; i++)
        #pragma unroll
        for (int j = 0; j < 8; j++)
            #pragma unroll
            for (int e = 0; e < 4; e++) acc[i][j][e] = 0.f;

    f16_load_chunk(tiles, tid, 0, m0, n0, K, A, B); CP_COMMIT();
    f16_load_chunk(tiles + F_STG, tid, 1, m0, n0, K, A, B); CP_COMMIT();
    f16_load_chunk(tiles + 2 * F_STG, tid, 2, m0, n0, K, A, B); CP_COMMIT();

    const int aRowL = lane & 15;
    const int aSegL = lane >> 4;
    const int bRowL = ((lane >> 4) & 1) * 8 + (lane & 7);
    const int bSegL = (lane >> 3) & 1;

    for (int c = 0; c < nCh; c++) {
        const uint32_t buf = tiles + (c % F_NSTAGE) * F_STG;
        CP_WAIT2();
        __syncthreads();
        if (c + 3 < nCh)
            f16_load_chunk(tiles + ((c + 3) % F_NSTAGE) * F_STG, tid, c + 3, m0, n0, K, A, B);
        CP_COMMIT();

        #pragma unroll
        for (int k16 = 0; k16 < 4; k16++) {
            uint32_t af[2][4], bf[4][4];
            #pragma unroll
            for (int mt = 0; mt < 2; mt++) {
                uint32_t row = wm + mt * 16 + aRowL;
                ldsm_x4(af[mt][0], af[mt][1], af[mt][2], af[mt][3],
                        buf + swz8(row, k16 * 2 + aSegL));
            }
            #pragma unroll
            for (int np = 0; np < 4; np++) {
                uint32_t row = wn + np * 16 + bRowL;
                ldsm_x4(bf[np][0], bf[np][1], bf[np][2], bf[np][3],
                        buf + F_OFF_B + swz8(row, k16 * 2 + bSegL));
            }
            #pragma unroll
            for (int mt = 0; mt < 2; mt++)
                #pragma unroll
                for (int np = 0; np < 4; np++)
                    #pragma unroll
                    for (int h = 0; h < 2; h++)
                        mma_f16(acc[mt][np * 2 + h], af[mt], &bf[np][h * 2]);
        }
        __syncthreads();
    }

    const int erow = lane >> 2, ecol = (lane & 3) * 2;

    if (mode == 0) {
        const int ncol = n0 + wn;
        const int zsel = ncol >> 10;
        const int hh = (ncol >> 6) & 15;
        #pragma unroll
        for (int mt = 0; mt < 2; mt++) {
            #pragma unroll
            for (int rsel = 0; rsel < 2; rsel++) {
                const int s = m0 + wm + mt * 16 + erow + rsel * 8;
                if (zsel == 2) {
                    __half* vb = Vout + ((size_t)hh * SEQ + s) * HD;
                    #pragma unroll
                    for (int nt = 0; nt < 8; nt++)
                        *(__half2*)(vb + nt * 8 + ecol) =
                            __floats2half2_rn(acc[mt][nt][rsel * 2], acc[mt][nt][rsel * 2 + 1]);
                } else {
                    __half* ob = (zsel == 0) ? (Qout + (size_t)s * DM + hh * HD)
                                             : (Kout + ((size_t)hh * SEQ + s) * HD);
                    #pragma unroll
                    for (int nt = 0; nt < 4; nt++) {
                        const int d0 = nt * 8 + ecol;
                        const float c0 = cosT[s * 32 + d0],     sn0 = sinT[s * 32 + d0];
                        const float c1 = cosT[s * 32 + d0 + 1], sn1 = sinT[s * 32 + d0 + 1];
                        const float a0 = acc[mt][nt][rsel * 2],     a1 = acc[mt][nt][rsel * 2 + 1];
                        const float b0 = acc[mt][nt + 4][rsel * 2], b1 = acc[mt][nt + 4][rsel * 2 + 1];
                        *(__half2*)(ob + d0) =
                            __floats2half2_rn(a0 * c0 - b0 * sn0, a1 * c1 - b1 * sn1);
                        *(__half2*)(ob + d0 + 32) =
                            __floats2half2_rn(b0 * c0 + a0 * sn0, b1 * c1 + a1 * sn1);
                    }
                }
            }
        }
    } else {
        #pragma unroll
        for (int mt = 0; mt < 2; mt++)
            #pragma unroll
            for (int nt = 0; nt < 8; nt++) {
                const float* d = acc[mt][nt];
                size_t r = (size_t)(m0 + wm + mt * 16 + erow);
                size_t col = n0 + wn + nt * 8 + ecol;
                *(float2*)&C[r * Nstride + col]       = make_float2(d[0], d[1]);
                *(float2*)&C[(r + 8) * Nstride + col] = make_float2(d[2], d[3]);
            }
    }
}

// ---------------- sparse attention: 4 queries / 256-thread block ----------------
// Logits via mma.sync; V phase scalar with smem-fed weights.
// Fully-masked (future) anchor tiles are skipped in staging, logits, and V.
__global__ void __launch_bounds__(256) attn(const int* __restrict__ anchors) {
    const int h = blockIdx.y;
    const int tid = threadIdx.x;
    const int ql = tid >> 6;
    const int j = tid & 63;
    const int s = blockIdx.x * QPB + ql;
    const int wq = (tid >> 5) & 1;
    const int lane = tid & 31;
    const int tig = lane & 3;

    __shared__ __align__(16) char sK[QPB][4 * 2048];   // 4 tiles x 16 rows x 128B
    __shared__ __half2 sqh[QPB][32];                   // q as half2
    __shared__ float2 sWO[QPB][64];                    // (weight, byteoff-as-float)
    __shared__ int stile[QPB][4];
    __shared__ float wred[QPB][2][2];
    __shared__ float spart[QPB][2][64];

    // q (half2) and tile indices
    if (j < 32)
        sqh[ql][j] = ((const __half2*)(g_qh16 + (size_t)s * DM + h * HD))[j];
    if (j < 4)
        stile[ql][j] = (j < NANCH) ? anchors[(h * SEQ + s) * NANCH + j] : (s >> 4);
    __syncthreads();

    const int t0 = stile[ql][0], t1 = stile[ql][1];
    const int t2 = stile[ql][2], t3 = stile[ql][3];
    // liveness: tile fully in the future (tile*16 > s) contributes nothing
    const bool l0 = (t0 << 4) <= s;
    const bool l1 = (t1 << 4) <= s;
    const bool l2 = (t2 << 4) <= s;
    // t3 = local tile, always live

    // stage live K tiles (2KB each, contiguous) with invariant per-thread offsets
    {
        const uint32_t sbase = smem_u32(sK[ql]);
        const char* hb = (const char*)g_khh + (size_t)h * SEQ * 128;
        const uint32_t so = (j >> 3) * 128 + (((j & 7) ^ (j >> 3)) << 4);
        const uint32_t go = j * 16;
        if (l0) {
            const char* p = hb + t0 * 2048 + go;
            cp16(sbase + so, p); cp16(sbase + 1024 + so, p + 1024);
        }
        if (l1) {
            const char* p = hb + t1 * 2048 + go;
            cp16(sbase + 2048 + so, p); cp16(sbase + 3072 + so, p + 1024);
        }
        if (l2) {
            const char* p = hb + t2 * 2048 + go;
            cp16(sbase + 4096 + so, p); cp16(sbase + 5120 + so, p + 1024);
        }
        {
            const char* p = hb + t3 * 2048 + go;
            cp16(sbase + 6144 + so, p); cp16(sbase + 7168 + so, p + 1024);
        }
    }
    CP_COMMIT();
    CP_WAIT0();
    __syncthreads();

    // B fragments: q replicated across all 8 n-columns
    uint32_t bq[4][2];
    #pragma unroll
    for (int c = 0; c < 4; c++) {
        bq[c][0] = *(const uint32_t*)&sqh[ql][c * 8 + tig];
        bq[c][1] = *(const uint32_t*)&sqh[ql][c * 8 + tig + 4];
    }

    // warp wq owns tiles {2wq, 2wq+1}; liveness of those m-tiles
    const bool lv0 = wq ? l2 : l0;
    const bool lv1 = wq ? true : l1;     // wq==1 second tile is local (live)

    // logits via mma: 2 m-tiles of 16 keys, 4 k-chunks each (skip dead tiles)
    const uint32_t sKb = smem_u32(sK[ql]);
    float lg[4];                             // keys: wq*32 + {r, r+8, 16+r, 24+r}
    #pragma unroll
    for (int t = 0; t < 2; t++) {
        const bool lv = t ? lv1 : lv0;
        if (lv) {
            float c4[4] = {0.f, 0.f, 0.f, 0.f};
            #pragma unroll
            for (int c = 0; c < 4; c++) {
                uint32_t a[4];
                ldsm_x4(a[0], a[1], a[2], a[3],
                        sKb + swz8(wq * 32 + t * 16 + (lane & 15), c * 2 + (lane >> 4)));
                mma_f16(c4, a, bq[c]);
            }
            lg[t * 2]     = c4[0] * 0.125f;
            lg[t * 2 + 1] = c4[2] * 0.125f;
        } else {
            lg[t * 2] = -1e30f;
            lg[t * 2 + 1] = -1e30f;
        }
    }

    const int r = lane >> 2;
    const int ti0 = wq ? t2 : t0, ti1 = wq ? t3 : t1;
    int kid[4] = {ti0 * 16 + r, ti0 * 16 + r + 8, ti1 * 16 + r, ti1 * 16 + r + 8};
    bool msk[4];
    #pragma unroll
    for (int i = 0; i < 4; i++) {
        msk[i] = kid[i] > s;
        if (msk[i]) lg[i] = -1e30f;
    }

    // softmax (each key duplicated x4 across the quad -> sum scaled by 0.25)
    float m = fmaxf(fmaxf(lg[0], lg[1]), fmaxf(lg[2], lg[3]));
    #pragma unroll
    for (int off = 16; off; off >>= 1) m = fmaxf(m, __shfl_xor_sync(~0u, m, off));
    if (lane == 0) wred[ql][0][wq] = m;
    __syncthreads();
    m = fmaxf(wred[ql][0][0], wred[ql][0][1]);

    float e[4];
    float lsum = 0.f;
    #pragma unroll
    for (int i = 0; i < 4; i++) {
        e[i] = msk[i] ? 0.f : __expf(lg[i] - m);
        lsum += e[i];
    }
    #pragma unroll
    for (int off = 16; off; off >>= 1) lsum += __shfl_xor_sync(~0u, lsum, off);
    if (lane == 0) wred[ql][1][wq] = lsum;
    __syncthreads();
    const float inv = 4.0f / (wred[ql][1][0] + wred[ql][1][1]);

    // quad leaders publish (weight, V byte offset) for their 4 keys
    if (tig == 0) {
        sWO[ql][wq * 32 + r]      = make_float2(e[0] * inv, __int_as_float(kid[0] << 7));
        sWO[ql][wq * 32 + r + 8]  = make_float2(e[1] * inv, __int_as_float(kid[1] << 7));
        sWO[ql][wq * 32 + r + 16] = make_float2(e[2] * inv, __int_as_float(kid[2] << 7));
        sWO[ql][wq * 32 + r + 24] = make_float2(e[3] * inv, __int_as_float(kid[3] << 7));
    }
    __syncwarp();

    // V phase: 2 keys per iteration; lanes 0-15 even key, 16-31 odd key.
    // Skip the 8-iteration half belonging to a dead tile (weights all 0).
    {
        const char* vb = (const char*)g_vhh + (size_t)h * SEQ * 128 + 8 * (lane & 15);
        const int sel = lane >> 4;           // 0 or 1
        float4 acc = make_float4(0.f, 0.f, 0.f, 0.f);
        if (lv0) {
            #pragma unroll
            for (int i = 0; i < 8; i++) {
                const float2 wo = sWO[ql][wq * 32 + 2 * i + sel];
                const __half2* vp = (const __half2*)(vb + __float_as_int(wo.y));
                const float2 v0 = __half22float2(vp[0]);
                const float2 v1 = __half22float2(vp[1]);
                acc.x = fmaf(wo.x, v0.x, acc.x);
                acc.y = fmaf(wo.x, v0.y, acc.y);
                acc.z = fmaf(wo.x, v1.x, acc.z);
                acc.w = fmaf(wo.x, v1.y, acc.w);
            }
        }
        if (lv1) {
            #pragma unroll
            for (int i = 8; i < 16; i++) {
                const float2 wo = sWO[ql][wq * 32 + 2 * i + sel];
                const __half2* vp = (const __half2*)(vb + __float_as_int(wo.y));
                const float2 v0 = __half22float2(vp[0]);
                const float2 v1 = __half22float2(vp[1]);
                acc.x = fmaf(wo.x, v0.x, acc.x);
                acc.y = fmaf(wo.x, v0.y, acc.y);
                acc.z = fmaf(wo.x, v1.x, acc.z);
                acc.w = fmaf(wo.x, v1.y, acc.w);
            }
        }
        acc.x += __shfl_xor_sync(~0u, acc.x, 16);
        acc.y += __shfl_xor_sync(~0u, acc.y, 16);
        acc.z += __shfl_xor_sync(~0u, acc.z, 16);
        acc.w += __shfl_xor_sync(~0u, acc.w, 16);
        if (lane < 16)
            ((float4*)spart[ql][wq])[lane] = acc;
    }
    __syncthreads();

    g_ath[(size_t)s * DM + h * HD + j] =
        __float2half(spart[ql][0][j] + spart[ql][1][j]);
}

// ---------------- launch ---------------------------------------------------------
extern "C" void kernel_launch(void* const* d_in, const int* in_sizes, int n_in,
                              void* d_out, int out_size)
{
    const float* x    = (const float*)d_in[0];
    const float* Wq   = (const float*)d_in[1];
    const float* Wk   = (const float*)d_in[2];
    const float* Wv   = (const float*)d_in[3];
    const float* Wo   = (const float*)d_in[4];
    const float* cosT = (const float*)d_in[5];
    const float* sinT = (const float*)d_in[6];
    const int* anchors = (const int*)d_in[7];
    float* out = (float*)d_out;

    const int SMEM_F = F_NSTAGE * F_STG;   // 128 KB
    cudaFuncSetAttribute(gemm_f16, cudaFuncAttributeMaxDynamicSharedMemorySize, SMEM_F);

    __half *xh = nullptr, *wth = nullptr, *woth = nullptr, *ath = nullptr;
    __half *qh = nullptr, *kh = nullptr, *vh = nullptr;
    cudaGetSymbolAddress((void**)&xh, g_xh);
    cudaGetSymbolAddress((void**)&wth, g_wth);
    cudaGetSymbolAddress((void**)&woth, g_woth);
    cudaGetSymbolAddress((void**)&ath, g_ath);
    cudaGetSymbolAddress((void**)&qh, g_qh16);
    cudaGetSymbolAddress((void**)&kh, g_khh);
    cudaGetSymbolAddress((void**)&vh, g_vhh);

    split_x<<<(SEQ * DM / 4) / 256, 256>>>(x);
    transpose_w<<<dim3(32, 32, 4), dim3(32, 32)>>>(Wq, Wk, Wv, Wo);

    // QKV GEMM with fused RoPE/split/fp16 epilogue
    gemm_f16<<<dim3(24, 16), 256, SMEM_F>>>(xh, wth, nullptr, 3072, DM, 0,
                                            qh, kh, vh, cosT, sinT);

    attn<<<dim3(SEQ / QPB, NH), 256>>>(anchors);

    // out = att @ Wo (plain fp32 epilogue)
    gemm_f16<<<dim3(8, 16), 256, SMEM_F>>>(ath, woth, out, DM, DM, 1,
                                           nullptr, nullptr, nullptr, nullptr, nullptr);
}